// round 9
// baseline (speedup 1.0000x reference)
#include <cuda_runtime.h>
#include <cuda_fp16.h>

#define B_    16
#define T_    2048
#define NTOK  (B_*T_)

typedef unsigned int u32;

// ---------------- scratch (static __device__, no allocations) ----------------
__device__ float g_x[NTOK*16];             // pre-attention residual x (fp32)
__device__ uint4 g_q4[NTOK];               // A-frag layout q: h0(qx,qy),(qz,0), h1(qx,qy),(qz,0)
__device__ uint2 g_kxy[NTOK];              // (h0 kx,ky), (h1 kx,ky)
__device__ unsigned short g_kz[B_*2*T_];   // [b][h][t] kz
__device__ unsigned short g_vT[B_*6*T_];   // [b][h*3+out][t] v transposed

__device__ __forceinline__ u32 hmul2(u32 a, u32 b){
    u32 d; asm("mul.rn.f16x2 %0,%1,%2;" : "=r"(d) : "r"(a), "r"(b)); return d;
}
__device__ __forceinline__ u32 hex2(u32 x){
    u32 y; asm("ex2.approx.f16x2 %0,%1;" : "=r"(y) : "r"(x)); return y;
}
__device__ __forceinline__ u32 packh2(float lo, float hi){
    __half2 h = __floats2half2_rn(lo, hi);
    return *reinterpret_cast<u32*>(&h);
}
// S = Q(16x8) @ K^T  -> f16 C fragment (C layout == A layout, enables chaining)
__device__ __forceinline__ void mma_s(u32& d0, u32& d1, u32 a0, u32 a1, u32 b){
    u32 z = 0u;
    asm("mma.sync.aligned.m16n8k8.row.col.f16.f16.f16.f16 {%0,%1},{%2,%3},{%4},{%5,%6};"
        : "=r"(d0), "=r"(d1) : "r"(a0), "r"(a1), "r"(b), "r"(z), "r"(z));
}
// O += P(16x8) @ V(8x8) -> f32 accum
__device__ __forceinline__ void mma_av(float* c, u32 a0, u32 a1, u32 b){
    asm("mma.sync.aligned.m16n8k8.row.col.f32.f16.f16.f32 {%0,%1,%2,%3},{%4,%5},{%6},{%0,%1,%2,%3};"
        : "+f"(c[0]), "+f"(c[1]), "+f"(c[2]), "+f"(c[3])
        : "r"(a0), "r"(a1), "r"(b));
}

// ============================================================================
// K1: embed + LN1 + QKV projection (one thread per token)
// ============================================================================
__global__ void __launch_bounds__(128) k1_qkv(
    const int* __restrict__ idx,
    const float* __restrict__ tok_emb,
    const float* __restrict__ pos_enc,
    const float* __restrict__ Wq,
    const float* __restrict__ Wk,
    const float* __restrict__ Wv,
    const float* __restrict__ ln1w,
    const float* __restrict__ ln1b)
{
    int tok = blockIdx.x * 128 + threadIdx.x;
    if (tok >= NTOK) return;
    int t = tok & (T_ - 1);
    int b = tok >> 11;

    float x[16];
    int vt = __ldg(idx + tok);
    #pragma unroll
    for (int i = 0; i < 8; i++) x[i]     = __ldg(tok_emb + vt*8 + i);
    #pragma unroll
    for (int i = 0; i < 8; i++) x[8 + i] = __ldg(pos_enc + t*8 + i);

    float m = 0.f;
    #pragma unroll
    for (int i = 0; i < 16; i++) m += x[i];
    m *= (1.f/16.f);
    float var = 0.f;
    #pragma unroll
    for (int i = 0; i < 16; i++){ float d = x[i] - m; var += d*d; }
    var *= (1.f/16.f);
    float rs = rsqrtf(var + 1e-5f);

    float h[16];
    #pragma unroll
    for (int i = 0; i < 16; i++)
        h[i] = (x[i] - m) * rs * __ldg(ln1w + i) + __ldg(ln1b + i);

    float4* xs = reinterpret_cast<float4*>(g_x + (size_t)tok*16);
    xs[0] = make_float4(x[0],  x[1],  x[2],  x[3]);
    xs[1] = make_float4(x[4],  x[5],  x[6],  x[7]);
    xs[2] = make_float4(x[8],  x[9],  x[10], x[11]);
    xs[3] = make_float4(x[12], x[13], x[14], x[15]);

    float q[6], k[6], vv[6];
    #pragma unroll
    for (int j = 0; j < 6; j++){
        float aq = 0.f, ak = 0.f, av = 0.f;
        #pragma unroll
        for (int d = 0; d < 8; d++){
            float hp = h[8 + d], ht = h[d];
            aq = fmaf(__ldg(Wq + j*8 + d), hp, aq);
            ak = fmaf(__ldg(Wk + j*8 + d), hp, ak);
            av = fmaf(__ldg(Wv + j*8 + d), ht, av);
        }
        q[j] = aq; k[j] = ak; vv[j] = av;
    }

    const float QS = 0.5773502691896258f * 1.4426950408889634f; // 1/sqrt(3)*log2e
    uint4 qo;
    qo.x = packh2(q[0]*QS, q[1]*QS);   // h0 (qx,qy)
    qo.y = packh2(q[2]*QS, 0.f);       // h0 (qz,0)
    qo.z = packh2(q[3]*QS, q[4]*QS);   // h1 (qx,qy)
    qo.w = packh2(q[5]*QS, 0.f);       // h1 (qz,0)
    g_q4[tok] = qo;

    g_kxy[tok] = make_uint2(packh2(k[0], k[1]), packh2(k[3], k[4]));
    __half kz0 = __float2half_rn(k[2]);
    __half kz1 = __float2half_rn(k[5]);
    g_kz[((size_t)b*2 + 0)*T_ + t] = *reinterpret_cast<unsigned short*>(&kz0);
    g_kz[((size_t)b*2 + 1)*T_ + t] = *reinterpret_cast<unsigned short*>(&kz1);
    #pragma unroll
    for (int h2 = 0; h2 < 2; h2++)
        #pragma unroll
        for (int o = 0; o < 3; o++){
            __half vh = __float2half_rn(vv[h2*3 + o]);
            g_vT[((size_t)b*6 + h2*3 + o)*T_ + t] = *reinterpret_cast<unsigned short*>(&vh);
        }
}

// ============================================================================
// K2: warp-MMA causal attention + epilogue.
// Block = 256 thr = 8 warps; one batch; 8 query tiles of 16 (pairing
// {4j+w, 131-4j-w} balances work across blocks exactly). Per step (8 kv
// positions, per head): 1 HMMA S=QK^T (f16), ex2.f16x2 x2, 1 HMMA O+=PV
// (f32, V has a ones-column so den rides along). Only the 2 diagonal steps
// are masked. KV tile staged in smem (~49KB). Grid = 16x16 = 256 blocks.
// ============================================================================
#define SKXY   0
#define SKZ    16384
#define SV     24576
#define SVSTR  4128                      // 2064 halfs: bank-shifted planes
#define SMOF   (24576 + 6*4128)          // 49344
#define SMEM_BYTES (SMOF + 224*4)        // 50240

__global__ void __launch_bounds__(256, 4) k2_attn(
    const float* __restrict__ Wo,
    const float* __restrict__ ln2w, const float* __restrict__ ln2b,
    const float* __restrict__ lnfw, const float* __restrict__ lnfb,
    const float* __restrict__ W1,   const float* __restrict__ b1,
    const float* __restrict__ W2,   const float* __restrict__ b2,
    const float* __restrict__ Wh,   const float* __restrict__ tok_emb,
    float* __restrict__ out)
{
    extern __shared__ char smem[];
    float* sM = reinterpret_cast<float*>(smem + SMOF);

    int tid = threadIdx.x;
    int b   = blockIdx.x >> 4;
    int jb  = blockIdx.x & 15;

    // ---- head matrix M = tok_emb @ Wh (14x16) ----
    if (tid < 224){
        int v = tid >> 4, i = tid & 15;
        float s = 0.f;
        #pragma unroll
        for (int d = 0; d < 8; d++)
            s = fmaf(__ldg(tok_emb + v*8 + d), __ldg(Wh + d*16 + i), s);
        sM[tid] = s;
    }

    // ---- stage KV tile ----
    {
        const uint4* s1 = reinterpret_cast<const uint4*>(g_kxy + (size_t)b*T_);
        uint4* d1 = reinterpret_cast<uint4*>(smem + SKXY);
        #pragma unroll
        for (int i = 0; i < 4; i++) d1[tid + 256*i] = s1[tid + 256*i];
        const uint4* s2 = reinterpret_cast<const uint4*>(g_kz + (size_t)b*2*T_);
        uint4* d2 = reinterpret_cast<uint4*>(smem + SKZ);
        d2[tid] = s2[tid]; d2[tid + 256] = s2[tid + 256];
        #pragma unroll
        for (int pl = 0; pl < 6; pl++){
            const uint4* s3 = reinterpret_cast<const uint4*>(g_vT + ((size_t)b*6 + pl)*T_);
            uint4* d3 = reinterpret_cast<uint4*>(smem + SV + pl*SVSTR);
            d3[tid] = s3[tid];
        }
    }
    __syncthreads();

    int w  = tid >> 5, l = tid & 31;
    int r4 = l >> 2, cc = l & 3;
    int tile = (w < 4) ? (4*jb + w) : (131 - 4*jb - w);
    int btok = b*T_;

    // Q fragments (A of m16n8k8: a0 rows 0-7, a1 rows 8-15; k-dims 2cc,2cc+1)
    uint4 qlo = g_q4[btok + tile*16 + r4];
    uint4 qhi = g_q4[btok + tile*16 + r4 + 8];
    u32 qa0[2], qa1[2];
    qa0[0] = (cc==0) ? qlo.x : (cc==1) ? qlo.y : 0u;
    qa1[0] = (cc==0) ? qhi.x : (cc==1) ? qhi.y : 0u;
    qa0[1] = (cc==0) ? qlo.z : (cc==1) ? qlo.w : 0u;
    qa1[1] = (cc==0) ? qhi.z : (cc==1) ? qhi.w : 0u;

    float acc[2][4] = {{0.f,0.f,0.f,0.f},{0.f,0.f,0.f,0.f}};

    bool ldK0 = (cc == 0), ldK1 = (cc == 1), ldV = (r4 < 3);
    u32 bvc = (r4 == 3) ? 0x3C003C00u : 0u;     // ones column -> denominator

    u32 mk;                                      // diagonal mask: pos_off <= row
    {
        __half2 md = __hle2(__floats2half2_rn(2.f*cc, 2.f*cc + 1.f),
                            __floats2half2_rn((float)r4, (float)r4));
        mk = *reinterpret_cast<u32*>(&md);
    }

    // per-lane smem byte offsets (advance 8 positions per step)
    int o_kxy = SKXY + r4*8;                     // +h*4       ; +64/step
    int o_kz  = SKZ  + r4*2;                     // +h*4096    ; +16/step
    int o_v   = SV   + cc*4;                     // +(h*3+r4)*SVSTR ; +16/step

    int nmain = 2*tile;
    #pragma unroll 2
    for (int s = 0; s < nmain; s++){
        #pragma unroll
        for (int h = 0; h < 2; h++){
            u32 bk = 0u;
            if (ldK0) bk = *reinterpret_cast<const u32*>(smem + o_kxy + h*4);
            if (ldK1) bk = (u32)*reinterpret_cast<const unsigned short*>(smem + o_kz + h*4096);
            u32 bv = bvc;
            if (ldV)  bv = *reinterpret_cast<const u32*>(smem + o_v + (h*3 + r4)*SVSTR);
            u32 s0, s1;
            mma_s(s0, s1, qa0[h], qa1[h], bk);
            u32 e0 = hex2(s0), e1 = hex2(s1);
            mma_av(acc[h], e0, e1, bv);
        }
        o_kxy += 64; o_kz += 16; o_v += 16;
    }
    // diagonal step A (positions 16*tile .. +7): low rows masked
    {
        #pragma unroll
        for (int h = 0; h < 2; h++){
            u32 bk = 0u;
            if (ldK0) bk = *reinterpret_cast<const u32*>(smem + o_kxy + h*4);
            if (ldK1) bk = (u32)*reinterpret_cast<const unsigned short*>(smem + o_kz + h*4096);
            u32 bv = bvc;
            if (ldV)  bv = *reinterpret_cast<const u32*>(smem + o_v + (h*3 + r4)*SVSTR);
            u32 s0, s1;
            mma_s(s0, s1, qa0[h], qa1[h], bk);
            u32 e0 = hmul2(hex2(s0), mk);
            u32 e1 = hex2(s1);
            mma_av(acc[h], e0, e1, bv);
        }
        o_kxy += 64; o_kz += 16; o_v += 16;
    }
    // diagonal step B (positions 16*tile+8 .. +15): low rows zero, high masked
    {
        #pragma unroll
        for (int h = 0; h < 2; h++){
            u32 bk = 0u;
            if (ldK0) bk = *reinterpret_cast<const u32*>(smem + o_kxy + h*4);
            if (ldK1) bk = (u32)*reinterpret_cast<const unsigned short*>(smem + o_kz + h*4096);
            u32 bv = bvc;
            if (ldV)  bv = *reinterpret_cast<const u32*>(smem + o_v + (h*3 + r4)*SVSTR);
            u32 s0, s1;
            mma_s(s0, s1, qa0[h], qa1[h], bk);
            u32 e1 = hmul2(hex2(s1), mk);
            mma_av(acc[h], 0u, e1, bv);
        }
    }
    __syncthreads();   // all KV reads done; overlay reduction area

    // ---- write O fragments: red[128 queries][8] = h0(ax,ay,az,den) h1(...) ----
    float* red = reinterpret_cast<float*>(smem);
    if (cc < 2){
        int qi = w*16 + r4;
        #pragma unroll
        for (int h = 0; h < 2; h++){
            red[(qi    )*8 + h*4 + cc*2 + 0] = acc[h][0];
            red[(qi    )*8 + h*4 + cc*2 + 1] = acc[h][1];
            red[(qi + 8)*8 + h*4 + cc*2 + 0] = acc[h][2];
            red[(qi + 8)*8 + h*4 + cc*2 + 1] = acc[h][3];
        }
    }
    __syncthreads();

    // ---- epilogue: 128 threads, one query each ----
    if (tid < 128){
        int w2 = tid >> 4, r = tid & 15;
        int tile2 = (w2 < 4) ? (4*jb + w2) : (131 - 4*jb - w2);
        int q = tile2*16 + r;
        const float* a = red + tid*8;
        float r0 = 1.f / a[3];
        float r1 = 1.f / a[7];
        float o[6];
        o[0] = a[0]*r0; o[1] = a[1]*r0; o[2] = a[2]*r0;   // head0
        o[3] = a[4]*r1; o[4] = a[5]*r1; o[5] = a[6]*r1;   // head1

        float x[16];
        const float4* xs = reinterpret_cast<const float4*>(g_x + ((size_t)btok + q)*16);
        float4 a0 = xs[0], a1 = xs[1], a2 = xs[2], a3 = xs[3];
        x[0]=a0.x; x[1]=a0.y; x[2]=a0.z; x[3]=a0.w;
        x[4]=a1.x; x[5]=a1.y; x[6]=a1.z; x[7]=a1.w;
        x[8]=a2.x; x[9]=a2.y; x[10]=a2.z; x[11]=a2.w;
        x[12]=a3.x; x[13]=a3.y; x[14]=a3.z; x[15]=a3.w;

        #pragma unroll
        for (int i = 0; i < 16; i++){
            float s = x[i];
            #pragma unroll
            for (int j = 0; j < 6; j++)
                s = fmaf(__ldg(Wo + i*6 + j), o[j], s);
            x[i] = s;
        }

        float m = 0.f;
        #pragma unroll
        for (int i = 0; i < 16; i++) m += x[i];
        m *= (1.f/16.f);
        float var = 0.f;
        #pragma unroll
        for (int i = 0; i < 16; i++){ float d = x[i] - m; var += d*d; }
        var *= (1.f/16.f);
        float rs = rsqrtf(var + 1e-5f);
        float h2[16];
        #pragma unroll
        for (int i = 0; i < 16; i++)
            h2[i] = (x[i] - m) * rs * __ldg(ln2w + i) + __ldg(ln2b + i);

        float g[3];
        #pragma unroll
        for (int j = 0; j < 3; j++){
            float f = __ldg(b1 + j);
            #pragma unroll
            for (int i = 0; i < 16; i++)
                f = fmaf(__ldg(W1 + j*16 + i), h2[i], f);
            g[j] = 0.5f * f * (1.f + erff(f * 0.7071067811865476f));
        }
        #pragma unroll
        for (int i = 0; i < 16; i++){
            float s = x[i] + __ldg(b2 + i);
            s = fmaf(__ldg(W2 + i*3 + 0), g[0], s);
            s = fmaf(__ldg(W2 + i*3 + 1), g[1], s);
            s = fmaf(__ldg(W2 + i*3 + 2), g[2], s);
            x[i] = s;
        }

        m = 0.f;
        #pragma unroll
        for (int i = 0; i < 16; i++) m += x[i];
        m *= (1.f/16.f);
        var = 0.f;
        #pragma unroll
        for (int i = 0; i < 16; i++){ float d = x[i] - m; var += d*d; }
        var *= (1.f/16.f);
        rs = rsqrtf(var + 1e-5f);
        float y[16];
        #pragma unroll
        for (int i = 0; i < 16; i++)
            y[i] = (x[i] - m) * rs * __ldg(lnfw + i) + __ldg(lnfb + i);

        float* op = out + ((size_t)btok + q)*14;
        #pragma unroll
        for (int v = 0; v < 14; v++){
            float s = 0.f;
            #pragma unroll
            for (int i = 0; i < 16; i++)
                s = fmaf(y[i], sM[v*16 + i], s);
            op[v] = s;
        }
    }
}

// ============================================================================
extern "C" void kernel_launch(void* const* d_in, const int* in_sizes, int n_in,
                              void* d_out, int out_size)
{
    const int*   idx  = (const int*)  d_in[0];
    const float* tokE = (const float*)d_in[1];
    const float* posE = (const float*)d_in[2];
    const float* Wq   = (const float*)d_in[3];
    const float* Wk   = (const float*)d_in[4];
    const float* Wv   = (const float*)d_in[5];
    const float* Wo   = (const float*)d_in[6];
    const float* ln1w = (const float*)d_in[7];
    const float* ln1b = (const float*)d_in[8];
    const float* ln2w = (const float*)d_in[9];
    const float* ln2b = (const float*)d_in[10];
    const float* lnfw = (const float*)d_in[11];
    const float* lnfb = (const float*)d_in[12];
    const float* W1   = (const float*)d_in[13];
    const float* b1   = (const float*)d_in[14];
    const float* W2   = (const float*)d_in[15];
    const float* b2   = (const float*)d_in[16];
    const float* Wh   = (const float*)d_in[17];
    float* out = (float*)d_out;

    static bool attr_set = false;
    if (!attr_set){
        cudaFuncSetAttribute(k2_attn,
                             cudaFuncAttributeMaxDynamicSharedMemorySize,
                             SMEM_BYTES);
        attr_set = true;
    }

    k1_qkv<<<NTOK/128, 128>>>(idx, tokE, posE, Wq, Wk, Wv, ln1w, ln1b);
    k2_attn<<<16*16, 256, SMEM_BYTES>>>(Wo, ln2w, ln2b, lnfw, lnfb,
                                        W1, b1, W2, b2, Wh, tokE, out);
}

// round 10
// speedup vs baseline: 1.0293x; 1.0293x over previous
#include <cuda_runtime.h>
#include <cuda_fp16.h>

#define B_    16
#define T_    2048
#define NTOK  (B_*T_)

typedef unsigned int u32;

// ---------------- scratch (static __device__, no allocations) ----------------
__device__ float g_x[NTOK*16];             // pre-attention residual x (fp32)
__device__ uint4 g_q4[NTOK];               // A-frag layout q: h0(qx,qy),(qz,0), h1(qx,qy),(qz,0)
__device__ uint2 g_kxy[NTOK];              // (h0 kx,ky), (h1 kx,ky)
__device__ unsigned short g_kz[B_*2*T_];   // [b][h][t] kz
__device__ unsigned short g_vT[B_*6*T_];   // [b][h*3+out][t] v transposed

__device__ __forceinline__ u32 hmul2(u32 a, u32 b){
    u32 d; asm("mul.rn.f16x2 %0,%1,%2;" : "=r"(d) : "r"(a), "r"(b)); return d;
}
__device__ __forceinline__ u32 hex2(u32 x){
    u32 y; asm("ex2.approx.f16x2 %0,%1;" : "=r"(y) : "r"(x)); return y;
}
__device__ __forceinline__ u32 packh2(float lo, float hi){
    __half2 h = __floats2half2_rn(lo, hi);
    return *reinterpret_cast<u32*>(&h);
}
// S = Q(16x8) @ K^T  -> f16 C fragment (C layout == A layout, enables chaining)
__device__ __forceinline__ void mma_s(u32& d0, u32& d1, u32 a0, u32 a1, u32 b){
    u32 z = 0u;
    asm("mma.sync.aligned.m16n8k8.row.col.f16.f16.f16.f16 {%0,%1},{%2,%3},{%4},{%5,%6};"
        : "=r"(d0), "=r"(d1) : "r"(a0), "r"(a1), "r"(b), "r"(z), "r"(z));
}
// O += P(16x8) @ V(8x8) -> f32 accum
__device__ __forceinline__ void mma_av(float* c, u32 a0, u32 a1, u32 b){
    asm("mma.sync.aligned.m16n8k8.row.col.f32.f16.f16.f32 {%0,%1,%2,%3},{%4,%5},{%6},{%0,%1,%2,%3};"
        : "+f"(c[0]), "+f"(c[1]), "+f"(c[2]), "+f"(c[3])
        : "r"(a0), "r"(a1), "r"(b));
}

// ============================================================================
// K1: embed + LN1 + QKV projection (one thread per token)
// ============================================================================
__global__ void __launch_bounds__(128) k1_qkv(
    const int* __restrict__ idx,
    const float* __restrict__ tok_emb,
    const float* __restrict__ pos_enc,
    const float* __restrict__ Wq,
    const float* __restrict__ Wk,
    const float* __restrict__ Wv,
    const float* __restrict__ ln1w,
    const float* __restrict__ ln1b)
{
    int tok = blockIdx.x * 128 + threadIdx.x;
    if (tok >= NTOK) return;
    int t = tok & (T_ - 1);
    int b = tok >> 11;

    float x[16];
    int vt = __ldg(idx + tok);
    #pragma unroll
    for (int i = 0; i < 8; i++) x[i]     = __ldg(tok_emb + vt*8 + i);
    #pragma unroll
    for (int i = 0; i < 8; i++) x[8 + i] = __ldg(pos_enc + t*8 + i);

    float m = 0.f;
    #pragma unroll
    for (int i = 0; i < 16; i++) m += x[i];
    m *= (1.f/16.f);
    float var = 0.f;
    #pragma unroll
    for (int i = 0; i < 16; i++){ float d = x[i] - m; var += d*d; }
    var *= (1.f/16.f);
    float rs = rsqrtf(var + 1e-5f);

    float h[16];
    #pragma unroll
    for (int i = 0; i < 16; i++)
        h[i] = (x[i] - m) * rs * __ldg(ln1w + i) + __ldg(ln1b + i);

    float4* xs = reinterpret_cast<float4*>(g_x + (size_t)tok*16);
    xs[0] = make_float4(x[0],  x[1],  x[2],  x[3]);
    xs[1] = make_float4(x[4],  x[5],  x[6],  x[7]);
    xs[2] = make_float4(x[8],  x[9],  x[10], x[11]);
    xs[3] = make_float4(x[12], x[13], x[14], x[15]);

    float q[6], k[6], vv[6];
    #pragma unroll
    for (int j = 0; j < 6; j++){
        float aq = 0.f, ak = 0.f, av = 0.f;
        #pragma unroll
        for (int d = 0; d < 8; d++){
            float hp = h[8 + d], ht = h[d];
            aq = fmaf(__ldg(Wq + j*8 + d), hp, aq);
            ak = fmaf(__ldg(Wk + j*8 + d), hp, ak);
            av = fmaf(__ldg(Wv + j*8 + d), ht, av);
        }
        q[j] = aq; k[j] = ak; vv[j] = av;
    }

    const float QS = 0.5773502691896258f * 1.4426950408889634f; // 1/sqrt(3)*log2e
    uint4 qo;
    qo.x = packh2(q[0]*QS, q[1]*QS);   // h0 (qx,qy)
    qo.y = packh2(q[2]*QS, 0.f);       // h0 (qz,0)
    qo.z = packh2(q[3]*QS, q[4]*QS);   // h1 (qx,qy)
    qo.w = packh2(q[5]*QS, 0.f);       // h1 (qz,0)
    g_q4[tok] = qo;

    g_kxy[tok] = make_uint2(packh2(k[0], k[1]), packh2(k[3], k[4]));
    __half kz0 = __float2half_rn(k[2]);
    __half kz1 = __float2half_rn(k[5]);
    g_kz[((size_t)b*2 + 0)*T_ + t] = *reinterpret_cast<unsigned short*>(&kz0);
    g_kz[((size_t)b*2 + 1)*T_ + t] = *reinterpret_cast<unsigned short*>(&kz1);
    #pragma unroll
    for (int h2 = 0; h2 < 2; h2++)
        #pragma unroll
        for (int o = 0; o < 3; o++){
            __half vh = __float2half_rn(vv[h2*3 + o]);
            g_vT[((size_t)b*6 + h2*3 + o)*T_ + t] = *reinterpret_cast<unsigned short*>(&vh);
        }
}

// ============================================================================
// K2: warp-MMA causal attention + per-warp epilogue.
// Block = 128 thr = 4 warps; warp owns ONE query tile of 16; block jb covers
// tiles {127-4jb-w}. Big tiles launch first (bid jb-major) so work-stealing
// backfills; no block-wide sync after the mainloop (per-warp smem scratch +
// __syncwarp only), so warp imbalance never stalls siblings. Double
// accumulator sets (even/odd steps) give 4 independent MMA chains per warp.
// Blocks stage only the KV prefix their largest tile needs.
// Grid = 32 jb x 16 batches = 512 blocks, 4 blocks/SM.
// ============================================================================
#define SKXY   0
#define SKZ    16384
#define SV     24576
#define SVSTR  4128                      // 2064 halfs: bank-shifted planes
#define SMOF   (24576 + 6*4128)          // 49344 (sM: 224 floats)
#define SSCR   (SMOF + 224*4)            // 50240 (scratch: 4 warps x 16 x 8 floats)
#define SMEM_BYTES (SSCR + 4*16*8*4)     // 52288

__global__ void __launch_bounds__(128, 4) k2_attn(
    const float* __restrict__ Wo,
    const float* __restrict__ ln2w, const float* __restrict__ ln2b,
    const float* __restrict__ lnfw, const float* __restrict__ lnfb,
    const float* __restrict__ W1,   const float* __restrict__ b1,
    const float* __restrict__ W2,   const float* __restrict__ b2,
    const float* __restrict__ Wh,   const float* __restrict__ tok_emb,
    float* __restrict__ out)
{
    extern __shared__ char smem[];
    float* sM  = reinterpret_cast<float*>(smem + SMOF);
    float* scr = reinterpret_cast<float*>(smem + SSCR);

    int tid = threadIdx.x;
    int b   = blockIdx.x & 15;           // batch
    int jb  = blockIdx.x >> 4;           // 0..31, jb=0 holds the biggest tiles
    int btok = b*T_;
    int npos = 2048 - 64*jb;             // KV prefix needed by this block

    // ---- head matrix M = tok_emb @ Wh (14x16) ----
    #pragma unroll
    for (int i = tid; i < 224; i += 128){
        int v = i >> 4, ii = i & 15;
        float s = 0.f;
        #pragma unroll
        for (int d = 0; d < 8; d++)
            s = fmaf(__ldg(tok_emb + v*8 + d), __ldg(Wh + d*16 + ii), s);
        sM[i] = s;
    }

    // ---- stage KV prefix [0, npos) ----
    {
        const uint4* s1 = reinterpret_cast<const uint4*>(g_kxy + (size_t)btok);
        uint4* d1 = reinterpret_cast<uint4*>(smem + SKXY);
        int c1 = npos >> 1;
        for (int i = tid; i < c1; i += 128) d1[i] = s1[i];
        int c2 = npos >> 3;
        #pragma unroll
        for (int h = 0; h < 2; h++){
            const uint4* s2 = reinterpret_cast<const uint4*>(g_kz + ((size_t)b*2 + h)*T_);
            uint4* d2 = reinterpret_cast<uint4*>(smem + SKZ + h*4096);
            for (int i = tid; i < c2; i += 128) d2[i] = s2[i];
        }
        #pragma unroll
        for (int pl = 0; pl < 6; pl++){
            const uint4* s3 = reinterpret_cast<const uint4*>(g_vT + ((size_t)b*6 + pl)*T_);
            uint4* d3 = reinterpret_cast<uint4*>(smem + SV + pl*SVSTR);
            for (int i = tid; i < c2; i += 128) d3[i] = s3[i];
        }
    }
    __syncthreads();

    int w  = tid >> 5, l = tid & 31;
    int r4 = l >> 2, cc = l & 3;
    int tile = 127 - (jb*4 + w);         // 0..127

    // Q fragments (A of m16n8k8: a0 rows 0-7, a1 rows 8-15; k-dims 2cc,2cc+1)
    uint4 qlo = g_q4[btok + tile*16 + r4];
    uint4 qhi = g_q4[btok + tile*16 + 8 + r4];
    u32 qa0[2], qa1[2];
    qa0[0] = (cc==0) ? qlo.x : (cc==1) ? qlo.y : 0u;
    qa1[0] = (cc==0) ? qhi.x : (cc==1) ? qhi.y : 0u;
    qa0[1] = (cc==0) ? qlo.z : (cc==1) ? qlo.w : 0u;
    qa1[1] = (cc==0) ? qhi.z : (cc==1) ? qhi.w : 0u;

    float accA[2][4] = {{0.f,0.f,0.f,0.f},{0.f,0.f,0.f,0.f}};
    float accB[2][4] = {{0.f,0.f,0.f,0.f},{0.f,0.f,0.f,0.f}};

    bool ldK0 = (cc == 0), ldK1 = (cc == 1), ldV = (r4 < 3);
    u32 bvc = (r4 == 3) ? 0x3C003C00u : 0u;     // ones column -> denominator

    u32 mk;                                      // diagonal mask: pos_off <= row
    {
        __half2 md = __hle2(__floats2half2_rn(2.f*cc, 2.f*cc + 1.f),
                            __floats2half2_rn((float)r4, (float)r4));
        mk = *reinterpret_cast<u32*>(&md);
    }

    // per-lane smem byte offsets (advance 8 positions per step)
    int o_kxy = SKXY + r4*8;                     // +h*4           ; +64/step
    int o_kz  = SKZ  + r4*2;                     // +h*4096        ; +16/step
    int o_v   = SV   + cc*4;                     // +(h*3+r4)*SVSTR; +16/step

    // mode: 0 = unmasked, 1 = diag step A (mask low rows), 2 = diag step B
    #define STEP(ACC, MODE)                                                        \
    {                                                                              \
        _Pragma("unroll")                                                          \
        for (int h = 0; h < 2; h++){                                               \
            u32 bk = 0u;                                                           \
            if (ldK0) bk = *reinterpret_cast<const u32*>(smem + o_kxy + h*4);      \
            if (ldK1) bk = (u32)*reinterpret_cast<const unsigned short*>(          \
                               smem + o_kz + h*4096);                              \
            u32 bv = bvc;                                                          \
            if (ldV)  bv = *reinterpret_cast<const u32*>(                          \
                               smem + o_v + (h*3 + r4)*SVSTR);                     \
            u32 s0, s1;                                                            \
            mma_s(s0, s1, qa0[h], qa1[h], bk);                                     \
            u32 e0 = hex2(s0), e1 = hex2(s1);                                      \
            if (MODE == 1) e0 = hmul2(e0, mk);                                     \
            if (MODE == 2){ e0 = 0u; e1 = hmul2(e1, mk); }                         \
            mma_av(ACC[h], e0, e1, bv);                                            \
        }                                                                          \
        o_kxy += 64; o_kz += 16; o_v += 16;                                        \
    }

    int nm = 2*tile;                    // unmasked steps (even)
    #pragma unroll 1
    for (int s = 0; s < nm; s += 2){
        STEP(accA, 0)
        STEP(accB, 0)
    }
    STEP(accA, 1)                        // diag: positions 16t..16t+7
    STEP(accB, 2)                        // diag: positions 16t+8..16t+15
    #undef STEP

    // merge accumulator sets
    #pragma unroll
    for (int h = 0; h < 2; h++)
        #pragma unroll
        for (int i = 0; i < 4; i++) accA[h][i] += accB[h][i];

    // ---- per-warp O-fragment redistribution (no block sync) ----
    float* sw = scr + w*(16*8);          // [query 0..15][h0 v0,v1,v2,den, h1 ...]
    if (cc < 2){
        #pragma unroll
        for (int h = 0; h < 2; h++){
            sw[ r4      *8 + h*4 + 2*cc + 0] = accA[h][0];
            sw[ r4      *8 + h*4 + 2*cc + 1] = accA[h][1];
            sw[(r4 + 8) *8 + h*4 + 2*cc + 0] = accA[h][2];
            sw[(r4 + 8) *8 + h*4 + 2*cc + 1] = accA[h][3];
        }
    }
    __syncwarp();

    // ---- per-warp epilogue: lanes 0-15, one query each ----
    if (l < 16){
        int q = tile*16 + l;
        const float* a = sw + l*8;
        float r0 = 1.f / a[3];
        float r1 = 1.f / a[7];
        float o[6];
        o[0] = a[0]*r0; o[1] = a[1]*r0; o[2] = a[2]*r0;   // head0
        o[3] = a[4]*r1; o[4] = a[5]*r1; o[5] = a[6]*r1;   // head1

        float x[16];
        const float4* xs = reinterpret_cast<const float4*>(g_x + ((size_t)btok + q)*16);
        float4 a0 = xs[0], a1 = xs[1], a2 = xs[2], a3 = xs[3];
        x[0]=a0.x; x[1]=a0.y; x[2]=a0.z; x[3]=a0.w;
        x[4]=a1.x; x[5]=a1.y; x[6]=a1.z; x[7]=a1.w;
        x[8]=a2.x; x[9]=a2.y; x[10]=a2.z; x[11]=a2.w;
        x[12]=a3.x; x[13]=a3.y; x[14]=a3.z; x[15]=a3.w;

        #pragma unroll
        for (int i = 0; i < 16; i++){
            float s = x[i];
            #pragma unroll
            for (int j = 0; j < 6; j++)
                s = fmaf(__ldg(Wo + i*6 + j), o[j], s);
            x[i] = s;
        }

        float m = 0.f;
        #pragma unroll
        for (int i = 0; i < 16; i++) m += x[i];
        m *= (1.f/16.f);
        float var = 0.f;
        #pragma unroll
        for (int i = 0; i < 16; i++){ float d = x[i] - m; var += d*d; }
        var *= (1.f/16.f);
        float rs = rsqrtf(var + 1e-5f);
        float h2[16];
        #pragma unroll
        for (int i = 0; i < 16; i++)
            h2[i] = (x[i] - m) * rs * __ldg(ln2w + i) + __ldg(ln2b + i);

        float g[3];
        #pragma unroll
        for (int j = 0; j < 3; j++){
            float f = __ldg(b1 + j);
            #pragma unroll
            for (int i = 0; i < 16; i++)
                f = fmaf(__ldg(W1 + j*16 + i), h2[i], f);
            g[j] = 0.5f * f * (1.f + erff(f * 0.7071067811865476f));
        }
        #pragma unroll
        for (int i = 0; i < 16; i++){
            float s = x[i] + __ldg(b2 + i);
            s = fmaf(__ldg(W2 + i*3 + 0), g[0], s);
            s = fmaf(__ldg(W2 + i*3 + 1), g[1], s);
            s = fmaf(__ldg(W2 + i*3 + 2), g[2], s);
            x[i] = s;
        }

        m = 0.f;
        #pragma unroll
        for (int i = 0; i < 16; i++) m += x[i];
        m *= (1.f/16.f);
        var = 0.f;
        #pragma unroll
        for (int i = 0; i < 16; i++){ float d = x[i] - m; var += d*d; }
        var *= (1.f/16.f);
        rs = rsqrtf(var + 1e-5f);
        float y[16];
        #pragma unroll
        for (int i = 0; i < 16; i++)
            y[i] = (x[i] - m) * rs * __ldg(lnfw + i) + __ldg(lnfb + i);

        float* op = out + ((size_t)btok + q)*14;
        #pragma unroll
        for (int v = 0; v < 14; v++){
            float s = 0.f;
            #pragma unroll
            for (int i = 0; i < 16; i++)
                s = fmaf(y[i], sM[v*16 + i], s);
            op[v] = s;
        }
    }
}

// ============================================================================
extern "C" void kernel_launch(void* const* d_in, const int* in_sizes, int n_in,
                              void* d_out, int out_size)
{
    const int*   idx  = (const int*)  d_in[0];
    const float* tokE = (const float*)d_in[1];
    const float* posE = (const float*)d_in[2];
    const float* Wq   = (const float*)d_in[3];
    const float* Wk   = (const float*)d_in[4];
    const float* Wv   = (const float*)d_in[5];
    const float* Wo   = (const float*)d_in[6];
    const float* ln1w = (const float*)d_in[7];
    const float* ln1b = (const float*)d_in[8];
    const float* ln2w = (const float*)d_in[9];
    const float* ln2b = (const float*)d_in[10];
    const float* lnfw = (const float*)d_in[11];
    const float* lnfb = (const float*)d_in[12];
    const float* W1   = (const float*)d_in[13];
    const float* b1   = (const float*)d_in[14];
    const float* W2   = (const float*)d_in[15];
    const float* b2   = (const float*)d_in[16];
    const float* Wh   = (const float*)d_in[17];
    float* out = (float*)d_out;

    static bool attr_set = false;
    if (!attr_set){
        cudaFuncSetAttribute(k2_attn,
                             cudaFuncAttributeMaxDynamicSharedMemorySize,
                             SMEM_BYTES);
        attr_set = true;
    }

    k1_qkv<<<NTOK/128, 128>>>(idx, tokE, posE, Wq, Wk, Wv, ln1w, ln1b);
    k2_attn<<<512, 128, SMEM_BYTES>>>(Wo, ln2w, ln2b, lnfw, lnfb,
                                      W1, b1, W2, b2, Wh, tokE, out);
}